// round 11
// baseline (speedup 1.0000x reference)
#include <cuda_runtime.h>
#include <math.h>

#define T_STEPS 8192
#define M_DIM   1024
#define N_DIM   2048

#define GBLOCKS        128
#define ROWS_PER_BLOCK 16    // N_DIM / GBLOCKS
#define RNN_THREADS    256

// Scratch for the batched input projection (allocation-free rule: device global).
__device__ float g_pre[(size_t)T_STEPS * N_DIM];

// DENSE per-block flags: 128 x 4B = 16 L2 sectors total (vs 128 padded
// sectors in R2) -> chip-wide poll traffic drops ~64x. Flags advance by
// exactly T_STEPS per launch, uniformly across blocks, so reading your OWN
// slot at launch start gives the epoch base; signed-distance compares make
// polling wraparound-safe. No resets -> graph-replay safe.
__device__ unsigned g_flags[GBLOCKS];

// ---------------------------------------------------------------------------
// Inline PTX helpers
// ---------------------------------------------------------------------------
__device__ __forceinline__ unsigned ld_acq(const unsigned* p) {
    unsigned v;
    asm volatile("ld.acquire.gpu.u32 %0, [%1];" : "=r"(v) : "l"(p) : "memory");
    return v;
}
__device__ __forceinline__ void st_rel(unsigned* p, unsigned v) {
    asm volatile("st.release.gpu.u32 [%0], %1;" :: "l"(p), "r"(v) : "memory");
}
__device__ __forceinline__ void fma2(unsigned long long& d,
                                     unsigned long long a,
                                     unsigned long long b) {
    asm("fma.rn.f32x2 %0, %1, %2, %3;" : "=l"(d) : "l"(a), "l"(b), "l"(d));
}
__device__ __forceinline__ unsigned long long add2(unsigned long long a,
                                                   unsigned long long b) {
    unsigned long long d;
    asm("add.rn.f32x2 %0, %1, %2;" : "=l"(d) : "l"(a), "l"(b));
    return d;
}
__device__ __forceinline__ float hsum2(unsigned long long v) {
    float lo, hi;
    asm("mov.b64 {%0, %1}, %2;" : "=f"(lo), "=f"(hi) : "l"(v));
    return lo + hi;
}

// ---------------------------------------------------------------------------
// Kernel 1: pre = X @ W_ih^T + (b_ih + b_hh)   (unchanged, proven, ~0.6 ms)
// ---------------------------------------------------------------------------
__global__ __launch_bounds__(256) void gemm_pre_kernel(
    const float* __restrict__ X,
    const float* __restrict__ Wih,
    const float* __restrict__ b_ih,
    const float* __restrict__ b_hh)
{
    __shared__ float As[8][128];
    __shared__ float Bs[8][128];

    const int tid = threadIdx.x;
    const int rowBase = blockIdx.x * 128;
    const int colBase = blockIdx.y * 128;
    const int tx = tid & 15;
    const int ty = tid >> 4;

    float acc[8][8];
#pragma unroll
    for (int i = 0; i < 8; i++)
#pragma unroll
        for (int j = 0; j < 8; j++) acc[i][j] = 0.0f;

    const int lr = tid >> 1;
    const int lq = (tid & 1) * 4;

    for (int k0 = 0; k0 < M_DIM; k0 += 8) {
        float4 av = *(const float4*)&X  [(size_t)(rowBase + lr) * M_DIM + k0 + lq];
        float4 bv = *(const float4*)&Wih[(size_t)(colBase + lr) * M_DIM + k0 + lq];

        __syncthreads();
        As[lq + 0][lr] = av.x;
        As[lq + 1][lr] = av.y;
        As[lq + 2][lr] = av.z;
        As[lq + 3][lr] = av.w;
        Bs[lq + 0][lr] = bv.x;
        Bs[lq + 1][lr] = bv.y;
        Bs[lq + 2][lr] = bv.z;
        Bs[lq + 3][lr] = bv.w;
        __syncthreads();

#pragma unroll
        for (int k = 0; k < 8; k++) {
            float4 a0 = ((const float4*)As[k])[ty];
            float4 a1 = ((const float4*)As[k])[ty + 16];
            float4 b0 = ((const float4*)Bs[k])[tx];
            float4 b1 = ((const float4*)Bs[k])[tx + 16];
            float a[8] = {a0.x, a0.y, a0.z, a0.w, a1.x, a1.y, a1.z, a1.w};
            float b[8] = {b0.x, b0.y, b0.z, b0.w, b1.x, b1.y, b1.z, b1.w};
#pragma unroll
            for (int i = 0; i < 8; i++)
#pragma unroll
                for (int j = 0; j < 8; j++)
                    acc[i][j] = fmaf(a[i], b[j], acc[i][j]);
        }
    }

    const int n0 = colBase + tx * 4;
    const int n1 = colBase + 64 + tx * 4;
    float bias[8];
#pragma unroll
    for (int j = 0; j < 4; j++) {
        bias[j]     = b_ih[n0 + j] + b_hh[n0 + j];
        bias[j + 4] = b_ih[n1 + j] + b_hh[n1 + j];
    }

#pragma unroll
    for (int i = 0; i < 8; i++) {
        int m = rowBase + ((i < 4) ? (ty * 4 + i) : (64 + ty * 4 + (i - 4)));
        float4 o0, o1;
        o0.x = acc[i][0] + bias[0];
        o0.y = acc[i][1] + bias[1];
        o0.z = acc[i][2] + bias[2];
        o0.w = acc[i][3] + bias[3];
        o1.x = acc[i][4] + bias[4];
        o1.y = acc[i][5] + bias[5];
        o1.z = acc[i][6] + bias[6];
        o1.w = acc[i][7] + bias[7];
        *(float4*)&g_pre[(size_t)m * N_DIM + n0] = o0;
        *(float4*)&g_pre[(size_t)m * N_DIM + n1] = o1;
    }
}

// ---------------------------------------------------------------------------
// Kernel 2: persistent RNN recurrence == R2's PROVEN kernel with exactly one
// change: the detect path. Warp 0 alone acquire-polls the 128 DENSE flags
// (lane L owns flags[4L..4L+3], scalar 4B loads, bitmask laggard re-poll);
// the pre-existing __syncthreads wakes the other warps (bar.sync composes
// with the pollers' acquires for cta-wide ordering — same edge R2 used for
// warps 4-7). Producer publish, W-in-regs, f32x2 compute: byte-identical.
// ---------------------------------------------------------------------------
__global__ __launch_bounds__(RNN_THREADS, 1) void rnn_kernel(
    const float* __restrict__ Whh,
    float* __restrict__ Y)
{
    const int tid  = threadIdx.x;
    const int b    = blockIdx.x;
    const int warp = tid >> 5;
    const int lane = tid & 31;
    const int row0 = b * ROWS_PER_BLOCK + 2 * warp;

    // Warp's two W_hh rows in registers, pre-packed as f32x2 pairs.
    unsigned long long wA[32], wB[32];
    {
        const ulonglong2* WA = (const ulonglong2*)(Whh + (size_t)row0 * N_DIM);
        const ulonglong2* WB = (const ulonglong2*)(Whh + (size_t)(row0 + 1) * N_DIM);
#pragma unroll
        for (int i = 0; i < 16; i++) {
            ulonglong2 va = WA[i * 32 + lane];
            ulonglong2 vb = WB[i * 32 + lane];
            wA[2 * i]     = va.x;
            wA[2 * i + 1] = va.y;
            wB[2 * i]     = vb.x;
            wB[2 * i + 1] = vb.y;
        }
    }

    // Epoch base from my own flag slot (uniform across blocks at launch start).
    const unsigned base = g_flags[b];

    // Step 0: h_0 = 0  =>  Y[0] = tanh(pre[0]).
    if (lane == 0) {
        const float2 p0 = *(const float2*)(g_pre + row0);
        float2 o;
        o.x = tanhf(p0.x);
        o.y = tanhf(p0.y);
        *(float2*)(Y + row0) = o;
    }
    __syncthreads();
    if (tid == 0) st_rel(&g_flags[b], base + 1u);

    // Prefetch pre for step 1.
    float2 pv = *(const float2*)(g_pre + (size_t)N_DIM + row0);

    for (int t = 1; t < T_STEPS; t++) {
        // Wait until every block has published h_{t-1} (flag >= base + t).
        const unsigned target = base + (unsigned)t;
        if (warp == 0) {
            const unsigned* f = &g_flags[lane * 4];
            unsigned m = 0;                      // 4-bit done mask
            while (m != 0xFu) {
#pragma unroll
                for (int k = 0; k < 4; k++) {
                    if (!((m >> k) & 1u) &&
                        (int)(ld_acq(f + k) - target) >= 0)
                        m |= (1u << k);
                }
            }
        }
        __syncthreads();

        // Dot products: rows row0, row0+1 against h_{t-1} = Y[t-1].
        const ulonglong2* Yp = (const ulonglong2*)(Y + (size_t)(t - 1) * N_DIM);
        unsigned long long acc00 = 0ull, acc01 = 0ull, acc10 = 0ull, acc11 = 0ull;
#pragma unroll
        for (int i = 0; i < 16; i++) {
            ulonglong2 hv = Yp[i * 32 + lane];
            fma2(acc00, wA[2 * i],     hv.x);
            fma2(acc01, wA[2 * i + 1], hv.y);
            fma2(acc10, wB[2 * i],     hv.x);
            fma2(acc11, wB[2 * i + 1], hv.y);
        }
        float r0 = hsum2(add2(acc00, acc01));
        float r1 = hsum2(add2(acc10, acc11));

#pragma unroll
        for (int o = 16; o; o >>= 1) {
            r0 += __shfl_xor_sync(0xffffffffu, r0, o);
            r1 += __shfl_xor_sync(0xffffffffu, r1, o);
        }

        // Prefetch next step's pre while the result is written.
        float2 pnext = pv;
        if (t + 1 < T_STEPS)
            pnext = *(const float2*)(g_pre + (size_t)(t + 1) * N_DIM + row0);

        if (lane == 0) {
            float2 o;
            o.x = tanhf(pv.x + r0);
            o.y = tanhf(pv.y + r1);
            *(float2*)(Y + (size_t)t * N_DIM + row0) = o;
        }
        pv = pnext;

        // Publish h_t: block barrier gives happens-before from all warps'
        // stores to tid0's gpu-scope release (R2-proven pattern).
        __syncthreads();
        if (tid == 0) st_rel(&g_flags[b], base + (unsigned)(t + 1));
    }
}

// ---------------------------------------------------------------------------
extern "C" void kernel_launch(void* const* d_in, const int* in_sizes, int n_in,
                              void* d_out, int out_size)
{
    const float* X   = (const float*)d_in[0];   // [T, M]
    const float* Wih = (const float*)d_in[1];   // [N, M]
    const float* Whh = (const float*)d_in[2];   // [N, N]
    const float* bih = (const float*)d_in[3];   // [N]
    const float* bhh = (const float*)d_in[4];   // [N]
    float* Y = (float*)d_out;                   // [T, N]

    dim3 ggrid(T_STEPS / 128, N_DIM / 128);
    gemm_pre_kernel<<<ggrid, 256>>>(X, Wih, bih, bhh);

    rnn_kernel<<<GBLOCKS, RNN_THREADS>>>(Whh, Y);
}

// round 12
// speedup vs baseline: 3.3800x; 3.3800x over previous
#include <cuda_runtime.h>
#include <math.h>

#define T_STEPS 8192
#define M_DIM   1024
#define N_DIM   2048

#define GBLOCKS        128
#define ROWS_PER_BLOCK 16    // N_DIM / GBLOCKS
#define RNN_THREADS    256

// Scratch for the batched input projection (allocation-free rule: device global).
__device__ float g_pre[(size_t)T_STEPS * N_DIM];

// ONE monotone arrival counter. Each block red.adds 1 after publishing each
// step (8192 adds/block/launch -> total 128*8192 == 0 mod 128, and the
// initial value is 0, so the counter is ALWAYS a multiple of 128 at launch
// boundaries). At launch start fewer than 128 step-0 arrivals can have
// occurred before any block reads its base (a block can only pass step 0
// once, and step 1 requires ALL 128), so flooring the first read to a
// multiple of 128 yields the same epoch base in every block. Wrap-safe via
// signed distance; no resets -> graph-replay safe; monotone -> deadlock-free.
__device__ unsigned g_ctr;

// ---------------------------------------------------------------------------
// Inline PTX helpers
// ---------------------------------------------------------------------------
__device__ __forceinline__ unsigned ld_acq(const unsigned* p) {
    unsigned v;
    asm volatile("ld.acquire.gpu.u32 %0, [%1];" : "=r"(v) : "l"(p) : "memory");
    return v;
}
__device__ __forceinline__ void red_rel_add1(unsigned* p) {
    asm volatile("red.release.gpu.global.add.u32 [%0], %1;"
                 :: "l"(p), "r"(1u) : "memory");
}
__device__ __forceinline__ void fma2(unsigned long long& d,
                                     unsigned long long a,
                                     unsigned long long b) {
    asm("fma.rn.f32x2 %0, %1, %2, %3;" : "=l"(d) : "l"(a), "l"(b), "l"(d));
}
__device__ __forceinline__ unsigned long long add2(unsigned long long a,
                                                   unsigned long long b) {
    unsigned long long d;
    asm("add.rn.f32x2 %0, %1, %2;" : "=l"(d) : "l"(a), "l"(b));
    return d;
}
__device__ __forceinline__ float hsum2(unsigned long long v) {
    float lo, hi;
    asm("mov.b64 {%0, %1}, %2;" : "=f"(lo), "=f"(hi) : "l"(v));
    return lo + hi;
}

// ---------------------------------------------------------------------------
// Kernel 1: pre = X @ W_ih^T + (b_ih + b_hh)   (unchanged, proven)
// ---------------------------------------------------------------------------
__global__ __launch_bounds__(256) void gemm_pre_kernel(
    const float* __restrict__ X,
    const float* __restrict__ Wih,
    const float* __restrict__ b_ih,
    const float* __restrict__ b_hh)
{
    __shared__ float As[8][128];
    __shared__ float Bs[8][128];

    const int tid = threadIdx.x;
    const int rowBase = blockIdx.x * 128;
    const int colBase = blockIdx.y * 128;
    const int tx = tid & 15;
    const int ty = tid >> 4;

    float acc[8][8];
#pragma unroll
    for (int i = 0; i < 8; i++)
#pragma unroll
        for (int j = 0; j < 8; j++) acc[i][j] = 0.0f;

    const int lr = tid >> 1;
    const int lq = (tid & 1) * 4;

    for (int k0 = 0; k0 < M_DIM; k0 += 8) {
        float4 av = *(const float4*)&X  [(size_t)(rowBase + lr) * M_DIM + k0 + lq];
        float4 bv = *(const float4*)&Wih[(size_t)(colBase + lr) * M_DIM + k0 + lq];

        __syncthreads();
        As[lq + 0][lr] = av.x;
        As[lq + 1][lr] = av.y;
        As[lq + 2][lr] = av.z;
        As[lq + 3][lr] = av.w;
        Bs[lq + 0][lr] = bv.x;
        Bs[lq + 1][lr] = bv.y;
        Bs[lq + 2][lr] = bv.z;
        Bs[lq + 3][lr] = bv.w;
        __syncthreads();

#pragma unroll
        for (int k = 0; k < 8; k++) {
            float4 a0 = ((const float4*)As[k])[ty];
            float4 a1 = ((const float4*)As[k])[ty + 16];
            float4 b0 = ((const float4*)Bs[k])[tx];
            float4 b1 = ((const float4*)Bs[k])[tx + 16];
            float a[8] = {a0.x, a0.y, a0.z, a0.w, a1.x, a1.y, a1.z, a1.w};
            float b[8] = {b0.x, b0.y, b0.z, b0.w, b1.x, b1.y, b1.z, b1.w};
#pragma unroll
            for (int i = 0; i < 8; i++)
#pragma unroll
                for (int j = 0; j < 8; j++)
                    acc[i][j] = fmaf(a[i], b[j], acc[i][j]);
        }
    }

    const int n0 = colBase + tx * 4;
    const int n1 = colBase + 64 + tx * 4;
    float bias[8];
#pragma unroll
    for (int j = 0; j < 4; j++) {
        bias[j]     = b_ih[n0 + j] + b_hh[n0 + j];
        bias[j + 4] = b_ih[n1 + j] + b_hh[n1 + j];
    }

#pragma unroll
    for (int i = 0; i < 8; i++) {
        int m = rowBase + ((i < 4) ? (ty * 4 + i) : (64 + ty * 4 + (i - 4)));
        float4 o0, o1;
        o0.x = acc[i][0] + bias[0];
        o0.y = acc[i][1] + bias[1];
        o0.z = acc[i][2] + bias[2];
        o0.w = acc[i][3] + bias[3];
        o1.x = acc[i][4] + bias[4];
        o1.y = acc[i][5] + bias[5];
        o1.z = acc[i][6] + bias[6];
        o1.w = acc[i][7] + bias[7];
        *(float4*)&g_pre[(size_t)m * N_DIM + n0] = o0;
        *(float4*)&g_pre[(size_t)m * N_DIM + n1] = o1;
    }
}

// ---------------------------------------------------------------------------
// Kernel 2: persistent RNN recurrence == R2's PROVEN compute with the barrier
// rebuilt on the two cheap LTS paths:
//   arrive:  red.release.gpu.add(ctr, 1)  (atomic-ALU aggregation, ~1 cyc/op)
//   detect:  ONE thread per block acquire-polls ctr with __nanosleep backoff
//            (sector nearly idle when the last add lands -> fast drain)
// ---------------------------------------------------------------------------
__global__ __launch_bounds__(RNN_THREADS, 1) void rnn_kernel(
    const float* __restrict__ Whh,
    float* __restrict__ Y)
{
    const int tid  = threadIdx.x;
    const int b    = blockIdx.x;
    const int warp = tid >> 5;
    const int lane = tid & 31;
    const int row0 = b * ROWS_PER_BLOCK + 2 * warp;

    // Warp's two W_hh rows in registers, pre-packed as f32x2 pairs.
    unsigned long long wA[32], wB[32];
    {
        const ulonglong2* WA = (const ulonglong2*)(Whh + (size_t)row0 * N_DIM);
        const ulonglong2* WB = (const ulonglong2*)(Whh + (size_t)(row0 + 1) * N_DIM);
#pragma unroll
        for (int i = 0; i < 16; i++) {
            ulonglong2 va = WA[i * 32 + lane];
            ulonglong2 vb = WB[i * 32 + lane];
            wA[2 * i]     = va.x;
            wA[2 * i + 1] = va.y;
            wB[2 * i]     = vb.x;
            wB[2 * i + 1] = vb.y;
        }
    }

    // Epoch base: floor the startup read to a multiple of 128 (see g_ctr
    // comment for why this is race-free and replay-safe).
    const unsigned base = ld_acq(&g_ctr) & ~127u;

    // Step 0: h_0 = 0  =>  Y[0] = tanh(pre[0]).
    if (lane == 0) {
        const float2 p0 = *(const float2*)(g_pre + row0);
        float2 o;
        o.x = tanhf(p0.x);
        o.y = tanhf(p0.y);
        *(float2*)(Y + row0) = o;
    }
    __syncthreads();                    // all stores done before arrival
    if (tid == 0) red_rel_add1(&g_ctr);

    // Prefetch pre for step 1.
    float2 pv = *(const float2*)(g_pre + (size_t)N_DIM + row0);

    for (int t = 1; t < T_STEPS; t++) {
        // Wait until all 128 blocks have published h_{t-1}.
        if (tid == 0) {
            const unsigned target = base + 128u * (unsigned)t;
            while ((int)(ld_acq(&g_ctr) - target) < 0) {
                __nanosleep(128);
            }
        }
        __syncthreads();

        // Dot products: rows row0, row0+1 against h_{t-1} = Y[t-1].
        const ulonglong2* Yp = (const ulonglong2*)(Y + (size_t)(t - 1) * N_DIM);
        unsigned long long acc00 = 0ull, acc01 = 0ull, acc10 = 0ull, acc11 = 0ull;
#pragma unroll
        for (int i = 0; i < 16; i++) {
            ulonglong2 hv = Yp[i * 32 + lane];
            fma2(acc00, wA[2 * i],     hv.x);
            fma2(acc01, wA[2 * i + 1], hv.y);
            fma2(acc10, wB[2 * i],     hv.x);
            fma2(acc11, wB[2 * i + 1], hv.y);
        }
        float r0 = hsum2(add2(acc00, acc01));
        float r1 = hsum2(add2(acc10, acc11));

#pragma unroll
        for (int o = 16; o; o >>= 1) {
            r0 += __shfl_xor_sync(0xffffffffu, r0, o);
            r1 += __shfl_xor_sync(0xffffffffu, r1, o);
        }

        // Prefetch next step's pre while the result is written.
        float2 pnext = pv;
        if (t + 1 < T_STEPS)
            pnext = *(const float2*)(g_pre + (size_t)(t + 1) * N_DIM + row0);

        if (lane == 0) {
            float2 o;
            o.x = tanhf(pv.x + r0);
            o.y = tanhf(pv.y + r1);
            *(float2*)(Y + (size_t)t * N_DIM + row0) = o;
        }
        pv = pnext;

        // Publish h_t: block barrier orders all warps' stores before the
        // release-arrival (same happens-before edge as R2, atomic form).
        __syncthreads();
        if (tid == 0) red_rel_add1(&g_ctr);
    }
}

// ---------------------------------------------------------------------------
extern "C" void kernel_launch(void* const* d_in, const int* in_sizes, int n_in,
                              void* d_out, int out_size)
{
    const float* X   = (const float*)d_in[0];   // [T, M]
    const float* Wih = (const float*)d_in[1];   // [N, M]
    const float* Whh = (const float*)d_in[2];   // [N, N]
    const float* bih = (const float*)d_in[3];   // [N]
    const float* bhh = (const float*)d_in[4];   // [N]
    float* Y = (float*)d_out;                   // [T, N]

    dim3 ggrid(T_STEPS / 128, N_DIM / 128);
    gemm_pre_kernel<<<ggrid, 256>>>(X, Wih, bih, bhh);

    rnn_kernel<<<GBLOCKS, RNN_THREADS>>>(Whh, Y);
}